// round 9
// baseline (speedup 1.0000x reference)
#include <cuda_runtime.h>
#include <cuda_bf16.h>
#include <cstdint>

#define SEM_DIMV 512
#define SEM_SIZEV 2048
#define ACO_DIMV 32
#define BB 16
#define TT 4096
#define NROWS (BB*TT)
#define DTOT 544
#define HALFV 4.0f
#define EPSV 1e-5f

#define TILE_M 64
#define N_TILES (NROWS/TILE_M)   // 1024
#define NC_COUNT 16              // 16 chunks of 128 codes
#define KK_COUNT 8
#define NSLOT 4
// slot: A hi 8KB @0, B hi 16KB @8192  -> 24KB
#define SLOT_BYTES 24576
#define ESQ_OFF (NSLOT*SLOT_BYTES)              // 98304
#define DYN_BYTES (ESQ_OFF + 8192 + 1024)       // ~105KB -> 2 CTAs/SM
#define DELTA_C 0.0088f

__device__ __align__(128) unsigned char g_A[N_TILES * 8 * 8192];   // 64MB
__device__ __align__(128) unsigned char g_B[128 * 16384];          // 2MB
__device__ float g_emb[SEM_SIZEV * SEM_DIMV];
__device__ float g_esq[SEM_SIZEV];
__device__ float g_candV[(size_t)NROWS * 32];                      // 8MB
__device__ int   g_candI[(size_t)NROWS * 32];                      // 8MB

// ------------------------------------------------------------------ helpers
__device__ __forceinline__ uint32_t smem_u32(const void* p) {
    uint32_t a;
    asm("{ .reg .u64 t; cvta.to.shared.u64 t, %1; cvt.u32.u64 %0, t; }" : "=r"(a) : "l"(p));
    return a;
}
__device__ __forceinline__ void mbar_init(uint32_t a, uint32_t cnt) {
    asm volatile("mbarrier.init.shared.b64 [%0], %1;" :: "r"(a), "r"(cnt) : "memory");
}
__device__ __forceinline__ void mbar_expect_tx(uint32_t a, uint32_t bytes) {
    asm volatile("mbarrier.arrive.expect_tx.shared.b64 _, [%0], %1;" :: "r"(a), "r"(bytes) : "memory");
}
__device__ __forceinline__ void mbar_arrive(uint32_t a) {
    asm volatile("mbarrier.arrive.shared.b64 _, [%0];" :: "r"(a) : "memory");
}
__device__ __forceinline__ void mbar_wait(uint32_t a, uint32_t parity) {
    asm volatile(
        "{\n\t.reg .pred P;\n\t"
        "W_%=:\n\t"
        "mbarrier.try_wait.parity.acquire.cta.shared::cta.b64 P, [%0], %1, 0x989680;\n\t"
        "@!P bra W_%=;\n\t}"
        :: "r"(a), "r"(parity) : "memory");
}
__device__ __forceinline__ void bulk_g2s(uint32_t dst, const void* src, uint32_t bytes, uint32_t mbar) {
    asm volatile("cp.async.bulk.shared::cluster.global.mbarrier::complete_tx::bytes [%0], [%1], %2, [%3];"
        :: "r"(dst), "l"(src), "r"(bytes), "r"(mbar) : "memory");
}

#define LDSM4(R0,R1,R2,R3,ADDR) \
    asm volatile("ldmatrix.sync.aligned.m8n8.x4.shared.b16 {%0,%1,%2,%3}, [%4];" \
        : "=r"(R0), "=r"(R1), "=r"(R2), "=r"(R3) : "r"(ADDR))

#define MMA16816(D, A0,A1,A2,A3, B0,B1) \
    asm volatile("mma.sync.aligned.m16n8k16.row.col.f32.bf16.bf16.f32 " \
        "{%0,%1,%2,%3},{%4,%5,%6,%7},{%8,%9},{%0,%1,%2,%3};" \
        : "+f"((D)[0]), "+f"((D)[1]), "+f"((D)[2]), "+f"((D)[3]) \
        : "r"(A0), "r"(A1), "r"(A2), "r"(A3), "r"(B0), "r"(B1))

__device__ __forceinline__ uint32_t pack_hi(float f0, float f1) {
    __nv_bfloat16 h0 = __float2bfloat16(f0);
    __nv_bfloat16 h1 = __float2bfloat16(f1);
    return (uint32_t)__bfloat16_as_ushort(h0) | ((uint32_t)__bfloat16_as_ushort(h1) << 16);
}
__device__ __forceinline__ void top2_ins(float v, int i, float* V, int* I) {
    if (v < V[0]) { V[1] = V[0]; I[1] = I[0]; V[0] = v; I[0] = i; }
    else if (v < V[1]) { V[1] = v; I[1] = i; }
}

// ---------------------------------------------------------------------------
// prep_embB: fused emb normalize + |e|^2 + swizzled bf16 codebook tiles
// block = one code, 128 threads
// ---------------------------------------------------------------------------
__global__ void prep_embB_kernel(const float* __restrict__ esum,
                                 const float* __restrict__ usage) {
    __shared__ float es[SEM_DIMV];
    __shared__ float red[128];
    int c = blockIdx.x, tid = threadIdx.x;
    float inv = 1.0f / fmaxf(usage[c], EPSV);
    float acc = 0.0f;
#pragma unroll
    for (int i = 0; i < 4; i++) {
        int d = tid + i * 128;
        float e = esum[c * SEM_DIMV + d] * inv;
        g_emb[c * SEM_DIMV + d] = e;
        es[d] = e;
        acc += e * e;
    }
    red[tid] = acc;
    __syncthreads();
    if (tid < 64) red[tid] += red[tid + 64];
    __syncthreads();
    if (tid < 32) {
        float v = red[tid] + red[tid + 32];
#pragma unroll
        for (int o = 16; o > 0; o >>= 1) v += __shfl_down_sync(0xffffffffu, v, o);
        if (tid == 0) g_esq[c] = v;
    }
    // swizzled bf16 tiles: code c -> (nc = c>>7, m = c&127); 8 kk x 8 chunks
    if (tid < 64) {
        int kk = tid >> 3, ch = tid & 7;
        int nc = c >> 7, m = c & 127;
        const float* src = es + kk * 64 + ch * 8;
        uint32_t hp[4];
#pragma unroll
        for (int i = 0; i < 4; i++) hp[i] = pack_hi(src[2*i], src[2*i+1]);
        uint32_t off = (uint32_t)m * 128 + ((uint32_t)(ch ^ (m & 7)) << 4);
        *(uint4*)(g_B + (size_t)(nc * 8 + kk) * 16384 + off) =
            make_uint4(hp[0], hp[1], hp[2], hp[3]);
    }
}

// ---------------------------------------------------------------------------
__global__ __launch_bounds__(256)
void prep_A_kernel(const float* __restrict__ x) {
    __shared__ float s[64 * 65];
    int tile = blockIdx.x >> 3, kk = blockIdx.x & 7;
    int b = tile >> 6, t0 = (tile & 63) * 64;
    int tid = threadIdx.x;
#pragma unroll
    for (int i = 0; i < 16; i++) {
        int idx = i * 256 + tid;
        int k = idx >> 6, m = idx & 63;
        s[k * 65 + m] = x[((size_t)(b * DTOT + kk * 64 + k)) * TT + t0 + m];
    }
    __syncthreads();
    size_t base = (size_t)blockIdx.x * 8192;
    for (int q = tid; q < 512; q += 256) {
        int m = q >> 3, c = q & 7;
        uint32_t hp[4];
#pragma unroll
        for (int i = 0; i < 4; i++)
            hp[i] = pack_hi(s[(c * 8 + 2*i) * 65 + m], s[(c * 8 + 2*i + 1) * 65 + m]);
        uint32_t off = (uint32_t)m * 128 + ((uint32_t)(c ^ (m & 7)) << 4);
        *(uint4*)(g_A + base + off) = make_uint4(hp[0], hp[1], hp[2], hp[3]);
    }
}

// ---------------------------------------------------------------------------
// coarse: 1-pass hi*hi GEMM, 4-deep pipeline, warp tile 32x32 (2M x 4N)
// refill duty round-robins across warps (warp s&7)
// ---------------------------------------------------------------------------
__global__ __launch_bounds__(256, 2)
void coarse_kernel() {
    extern __shared__ unsigned char dynraw[];
    __shared__ __align__(8) unsigned long long bars[2 * NSLOT];

    uint32_t raw = smem_u32(dynraw);
    uint32_t abase = (raw + 1023u) & ~1023u;
    float* esq_s = (float*)(dynraw + (abase - raw) + ESQ_OFF);
    uint32_t barF[NSLOT], barE[NSLOT];
#pragma unroll
    for (int i = 0; i < NSLOT; i++) {
        barF[i] = smem_u32(&bars[i]);
        barE[i] = smem_u32(&bars[NSLOT + i]);
    }

    int tid = threadIdx.x;
    int lane = tid & 31;
    int wid = tid >> 5;
    int warpM = wid >> 2, warpN = wid & 3;     // 2(M) x 4(N), warp 32x32
    int tile = blockIdx.x;

    if (tid == 0) {
#pragma unroll
        for (int i = 0; i < NSLOT; i++) { mbar_init(barF[i], 1); mbar_init(barE[i], 8); }
    }
    for (int i = tid; i < SEM_SIZEV; i += 256) esq_s[i] = g_esq[i];
    __syncthreads();

    const unsigned char* srcA = g_A + (size_t)tile * (8 * 8192);

    if (tid == 0) {
#pragma unroll
        for (int s = 0; s < NSLOT; s++) {      // nc0, kk 0..3
            mbar_expect_tx(barF[s], SLOT_BYTES);
            bulk_g2s(abase + s * SLOT_BYTES, srcA + (size_t)s * 8192, 8192, barF[s]);
            bulk_g2s(abase + s * SLOT_BYTES + 8192, g_B + (size_t)s * 16384, 16384, barF[s]);
        }
    }

    // hoisted ldmatrix geometry
    uint32_t sw = lane & 7;
    uint32_t aRowOff = (uint32_t)(warpM * 32 + (lane & 15)) * 128;
    uint32_t aAdd = lane >> 4;
    uint32_t bRowOff = (uint32_t)(warpN * 32 + (lane & 7) + ((lane & 16) >> 1)) * 128;
    uint32_t bAdd = (lane >> 3) & 1;
    uint32_t caOff[4], cbOff[4];
#pragma unroll
    for (int j = 0; j < 4; j++) {
        caOff[j] = aRowOff + (uint32_t)(((2 * j + aAdd) ^ sw) << 4);
        cbOff[j] = 8192u + bRowOff + (uint32_t)(((2 * j + bAdd) ^ sw) << 4);
    }

    float tV[2][2][2];
    int   tI[2][2][2];
#pragma unroll
    for (int mi = 0; mi < 2; mi++)
#pragma unroll
        for (int h = 0; h < 2; h++) {
            tV[mi][h][0] = tV[mi][h][1] = 3.4e38f;
            tI[mi][h][0] = tI[mi][h][1] = 0;
        }

    for (int nc = 0; nc < NC_COUNT; nc++) {
        float acc[2][4][4];
#pragma unroll
        for (int mi = 0; mi < 2; mi++)
#pragma unroll
            for (int nf = 0; nf < 4; nf++)
#pragma unroll
                for (int e = 0; e < 4; e++) acc[mi][nf][e] = 0.0f;

#pragma unroll
        for (int kk = 0; kk < KK_COUNT; kk++) {
            int s = nc * 8 + kk;
            int slot = kk & 3;
            uint32_t p = (uint32_t)(((nc << 1) + (kk >> 2)) & 1);
            mbar_wait(barF[slot], p);
            uint32_t sb = abase + slot * SLOT_BYTES;

#pragma unroll
            for (int j = 0; j < 4; j++) {
                uint32_t ar[2][4], br[2][4];
#pragma unroll
                for (int mi = 0; mi < 2; mi++)
                    LDSM4(ar[mi][0], ar[mi][1], ar[mi][2], ar[mi][3],
                          sb + caOff[j] + mi * 2048);
#pragma unroll
                for (int nf2 = 0; nf2 < 2; nf2++)
                    LDSM4(br[nf2][0], br[nf2][1], br[nf2][2], br[nf2][3],
                          sb + cbOff[j] + nf2 * 2048);
#pragma unroll
                for (int mi = 0; mi < 2; mi++)
#pragma unroll
                    for (int nf2 = 0; nf2 < 2; nf2++) {
                        MMA16816(acc[mi][2 * nf2],     ar[mi][0], ar[mi][1], ar[mi][2], ar[mi][3],
                                 br[nf2][0], br[nf2][1]);
                        MMA16816(acc[mi][2 * nf2 + 1], ar[mi][0], ar[mi][1], ar[mi][2], ar[mi][3],
                                 br[nf2][2], br[nf2][3]);
                    }
            }
            if (lane == 0) mbar_arrive(barE[slot]);

            // refill by warp (s & 7): spreads producer overhead across warps
            if (wid == (s & 7) && lane == 0 && s + NSLOT < NC_COUNT * KK_COUNT) {
                mbar_wait(barE[slot], p);
                int s2 = s + NSLOT;
                int nc2 = s2 >> 3, kk2 = s2 & 7;
                mbar_expect_tx(barF[slot], SLOT_BYTES);
                bulk_g2s(sb, srcA + (size_t)kk2 * 8192, 8192, barF[slot]);
                bulk_g2s(sb + 8192, g_B + (size_t)(nc2 * 8 + kk2) * 16384, 16384, barF[slot]);
            }
        }

        // score this 128-code chunk
        int cbase = nc * 128 + warpN * 32 + (lane & 3) * 2;
#pragma unroll
        for (int nf = 0; nf < 4; nf++) {
            float eq0 = esq_s[cbase + nf * 8 + 0];
            float eq1 = esq_s[cbase + nf * 8 + 1];
            int c0 = cbase + nf * 8, c1 = c0 + 1;
#pragma unroll
            for (int mi = 0; mi < 2; mi++) {
                top2_ins(eq0 - 2.0f * acc[mi][nf][0], c0, tV[mi][0], tI[mi][0]);
                top2_ins(eq1 - 2.0f * acc[mi][nf][1], c1, tV[mi][0], tI[mi][0]);
                top2_ins(eq0 - 2.0f * acc[mi][nf][2], c0, tV[mi][1], tI[mi][1]);
                top2_ins(eq1 - 2.0f * acc[mi][nf][3], c1, tV[mi][1], tI[mi][1]);
            }
        }
    }

    // write 32 candidates per row
    int slotIdx = (warpN * 4 + (lane & 3)) * 2;
#pragma unroll
    for (int mi = 0; mi < 2; mi++)
#pragma unroll
        for (int h = 0; h < 2; h++) {
            int r = tile * 64 + warpM * 32 + mi * 16 + h * 8 + (lane >> 2);
            size_t base = (size_t)r * 32 + slotIdx;
            g_candV[base]     = tV[mi][h][0];
            g_candV[base + 1] = tV[mi][h][1];
            g_candI[base]     = tI[mi][h][0];
            g_candI[base + 1] = tI[mi][h][1];
        }
}

// ---------------------------------------------------------------------------
// rescore: warp per row; margin filter + exact fp32 rescore; sem output
// + fused ACO quantizer (1024 threads = 32 j x 32 t, one element each)
// ---------------------------------------------------------------------------
#define XS_PITCH 513
#define DYN_RESCORE (32 * XS_PITCH * 4)

__global__ __launch_bounds__(1024)
void rescore_kernel(const float* __restrict__ x,
                    const float* __restrict__ noise,
                    const float* __restrict__ probs_sem,
                    const float* __restrict__ probs_aco,
                    float* __restrict__ outq,
                    float* __restrict__ outc) {
    extern __shared__ float xs[];
    __shared__ int codes_s[32];

    int tid = threadIdx.x;
    int lane = tid & 31;
    int w = tid >> 5;
    int b = blockIdx.x >> 7;
    int t0 = (blockIdx.x & 127) * 32;

    // ---- fused ACO path: element (j = w, t = t0+lane) ----
    {
        int j = w, tl = lane;
        float a = x[((size_t)b * DTOT + SEM_DIMV + j) * TT + t0 + tl];
        float zb = tanhf(a) * HALFV;
        float pa = probs_aco[b];
        float zout;
        if (pa < 0.5f) {
            zout = rintf(zb);
        } else if (pa < 0.75f) {
            float ns = (noise[((size_t)b * ACO_DIMV + j) * TT + t0 + tl] * 2.0f - 1.0f) * (HALFV / 9.0f);
            zout = fminf(fmaxf(zb + ns, -HALFV), HALFV);
        } else {
            zout = zb;
        }
        float code = fminf(fmaxf(rintf(zout + HALFV), 0.0f), 8.0f);
        outq[((size_t)b * DTOT + SEM_DIMV + j) * TT + t0 + tl] = zout * 0.25f;
        outc[((size_t)b * 33 + 1 + j) * TT + t0 + tl] = code;
    }

    const float* xb = x + (size_t)b * DTOT * TT + t0;

#pragma unroll
    for (int it = 0; it < 16; it++) {
        int idx = it * 1024 + tid;
        int d = idx >> 5, t = idx & 31;
        xs[t * XS_PITCH + d] = xb[(size_t)d * TT + t];
    }
    __syncthreads();

    int r = blockIdx.x * 32 + w;
    float candV = g_candV[(size_t)r * 32 + lane];
    int   candI = g_candI[(size_t)r * 32 + lane];
    float candE = g_esq[candI];

    float xsq = 0.0f;
#pragma unroll
    for (int i = 0; i < 16; i++) {
        float v = xs[w * XS_PITCH + i * 32 + lane];
        xsq += v * v;
    }
#pragma unroll
    for (int o = 16; o > 0; o >>= 1) xsq += __shfl_xor_sync(0xffffffffu, xsq, o);

    float delta = DELTA_C * sqrtf(xsq * candE);
    float ub = candV + delta;
#pragma unroll
    for (int o = 16; o > 0; o >>= 1) ub = fminf(ub, __shfl_xor_sync(0xffffffffu, ub, o));
    unsigned pm = __ballot_sync(0xffffffffu, candV - delta <= ub);

    float bestd = 3.4e38f;
    int bestc = SEM_SIZEV;
    while (pm) {
        int p = __ffs(pm) - 1;
        pm &= pm - 1;
        int c = __shfl_sync(0xffffffffu, candI, p);
        float eq = __shfl_sync(0xffffffffu, candE, p);
        const float* er = g_emb + (size_t)c * SEM_DIMV;
        float dot = 0.0f;
#pragma unroll
        for (int i = 0; i < 16; i++)
            dot += xs[w * XS_PITCH + i * 32 + lane] * er[i * 32 + lane];
#pragma unroll
        for (int o = 16; o > 0; o >>= 1) dot += __shfl_xor_sync(0xffffffffu, dot, o);
        float d2 = eq - 2.0f * dot;
        if (d2 < bestd || (d2 == bestd && c < bestc)) { bestd = d2; bestc = c; }
    }
    if (lane == 0) {
        codes_s[w] = bestc;
        outc[(size_t)b * 33 * TT + t0 + w] = (float)bestc;
    }
    __syncthreads();

    float psem = probs_sem[b];
    float* outqb = outq + (size_t)b * DTOT * TT + t0;
    if (psem < 0.5f) {
        int c = codes_s[w];
        const float* er = g_emb + (size_t)c * SEM_DIMV;
        __syncthreads();
#pragma unroll
        for (int i = 0; i < 16; i++)
            xs[w * XS_PITCH + i * 32 + lane] = er[i * 32 + lane];
        __syncthreads();
    }
#pragma unroll
    for (int it = 0; it < 16; it++) {
        int idx = it * 1024 + tid;
        int d = idx >> 5, t = idx & 31;
        outqb[(size_t)d * TT + t] = xs[t * XS_PITCH + d];
    }
}

// ---------------------------------------------------------------------------
extern "C" void kernel_launch(void* const* d_in, const int* in_sizes, int n_in,
                              void* d_out, int out_size) {
    const float* x     = (const float*)d_in[0];
    const float* esum  = (const float*)d_in[1];
    const float* usage = (const float*)d_in[2];
    const float* noise = (const float*)d_in[3];
    const float* psem  = (const float*)d_in[4];
    const float* paco  = (const float*)d_in[5];

    float* outq = (float*)d_out;
    float* outc = outq + (size_t)BB * DTOT * TT;

    cudaFuncSetAttribute(coarse_kernel,
                         cudaFuncAttributeMaxDynamicSharedMemorySize, DYN_BYTES);
    cudaFuncSetAttribute(rescore_kernel,
                         cudaFuncAttributeMaxDynamicSharedMemorySize, DYN_RESCORE);

    prep_embB_kernel<<<SEM_SIZEV, 128>>>(esum, usage);
    prep_A_kernel<<<N_TILES * 8, 256>>>(x);
    coarse_kernel<<<N_TILES, 256, DYN_BYTES>>>();
    rescore_kernel<<<NROWS / 32, 1024, DYN_RESCORE>>>(x, noise, psem, paco, outq, outc);
}

// round 10
// speedup vs baseline: 1.1750x; 1.1750x over previous
#include <cuda_runtime.h>
#include <cuda_bf16.h>
#include <cstdint>

#define SEM_DIMV 512
#define SEM_SIZEV 2048
#define ACO_DIMV 32
#define BB 16
#define TT 4096
#define NROWS (BB*TT)
#define DTOT 544
#define HALFV 4.0f
#define EPSV 1e-5f

#define TILE_M 64
#define N_TILES (NROWS/TILE_M)   // 1024
#define NC_COUNT 16              // 16 chunks of 128 codes
#define KK_COUNT 8
#define NSLOT 4
// slot: A hi 8KB @0, B hi 16KB @8192  -> 24KB
#define SLOT_BYTES 24576
#define ESQ_OFF (NSLOT*SLOT_BYTES)              // 98304
#define DYN_BYTES (ESQ_OFF + 8192 + 1024)       // ~105KB -> 2 CTAs/SM
#define DELTA_C 0.0088f

__device__ __align__(128) unsigned char g_A[N_TILES * 8 * 8192];   // 64MB
__device__ __align__(128) unsigned char g_B[128 * 16384];          // 2MB
__device__ float g_emb[SEM_SIZEV * SEM_DIMV];
__device__ float g_esq[SEM_SIZEV];
__device__ float g_candV[(size_t)NROWS * 32];                      // 8MB
__device__ int   g_candI[(size_t)NROWS * 32];                      // 8MB

// ------------------------------------------------------------------ helpers
__device__ __forceinline__ uint32_t smem_u32(const void* p) {
    uint32_t a;
    asm("{ .reg .u64 t; cvta.to.shared.u64 t, %1; cvt.u32.u64 %0, t; }" : "=r"(a) : "l"(p));
    return a;
}
__device__ __forceinline__ void mbar_init(uint32_t a, uint32_t cnt) {
    asm volatile("mbarrier.init.shared.b64 [%0], %1;" :: "r"(a), "r"(cnt) : "memory");
}
__device__ __forceinline__ void mbar_expect_tx(uint32_t a, uint32_t bytes) {
    asm volatile("mbarrier.arrive.expect_tx.shared.b64 _, [%0], %1;" :: "r"(a), "r"(bytes) : "memory");
}
__device__ __forceinline__ void mbar_arrive(uint32_t a) {
    asm volatile("mbarrier.arrive.shared.b64 _, [%0];" :: "r"(a) : "memory");
}
__device__ __forceinline__ void mbar_wait(uint32_t a, uint32_t parity) {
    asm volatile(
        "{\n\t.reg .pred P;\n\t"
        "W_%=:\n\t"
        "mbarrier.try_wait.parity.acquire.cta.shared::cta.b64 P, [%0], %1, 0x989680;\n\t"
        "@!P bra W_%=;\n\t}"
        :: "r"(a), "r"(parity) : "memory");
}
__device__ __forceinline__ void bulk_g2s(uint32_t dst, const void* src, uint32_t bytes, uint32_t mbar) {
    asm volatile("cp.async.bulk.shared::cluster.global.mbarrier::complete_tx::bytes [%0], [%1], %2, [%3];"
        :: "r"(dst), "l"(src), "r"(bytes), "r"(mbar) : "memory");
}

#define LDSM4(R0,R1,R2,R3,ADDR) \
    asm volatile("ldmatrix.sync.aligned.m8n8.x4.shared.b16 {%0,%1,%2,%3}, [%4];" \
        : "=r"(R0), "=r"(R1), "=r"(R2), "=r"(R3) : "r"(ADDR))

#define MMA16816(D, A0,A1,A2,A3, B0,B1) \
    asm volatile("mma.sync.aligned.m16n8k16.row.col.f32.bf16.bf16.f32 " \
        "{%0,%1,%2,%3},{%4,%5,%6,%7},{%8,%9},{%0,%1,%2,%3};" \
        : "+f"((D)[0]), "+f"((D)[1]), "+f"((D)[2]), "+f"((D)[3]) \
        : "r"(A0), "r"(A1), "r"(A2), "r"(A3), "r"(B0), "r"(B1))

__device__ __forceinline__ uint32_t pack_hi(float f0, float f1) {
    __nv_bfloat16 h0 = __float2bfloat16(f0);
    __nv_bfloat16 h1 = __float2bfloat16(f1);
    return (uint32_t)__bfloat16_as_ushort(h0) | ((uint32_t)__bfloat16_as_ushort(h1) << 16);
}
__device__ __forceinline__ void top2_ins(float v, int i, float* V, int* I) {
    if (v < V[0]) { V[1] = V[0]; I[1] = I[0]; V[0] = v; I[0] = i; }
    else if (v < V[1]) { V[1] = v; I[1] = i; }
}

// ---------------------------------------------------------------------------
// prep_embB: fused emb normalize + |e|^2 + swizzled bf16 codebook tiles
// ---------------------------------------------------------------------------
__global__ void prep_embB_kernel(const float* __restrict__ esum,
                                 const float* __restrict__ usage) {
    __shared__ float es[SEM_DIMV];
    __shared__ float red[128];
    int c = blockIdx.x, tid = threadIdx.x;
    float inv = 1.0f / fmaxf(usage[c], EPSV);
    float acc = 0.0f;
#pragma unroll
    for (int i = 0; i < 4; i++) {
        int d = tid + i * 128;
        float e = esum[c * SEM_DIMV + d] * inv;
        g_emb[c * SEM_DIMV + d] = e;
        es[d] = e;
        acc += e * e;
    }
    red[tid] = acc;
    __syncthreads();
    if (tid < 64) red[tid] += red[tid + 64];
    __syncthreads();
    if (tid < 32) {
        float v = red[tid] + red[tid + 32];
#pragma unroll
        for (int o = 16; o > 0; o >>= 1) v += __shfl_down_sync(0xffffffffu, v, o);
        if (tid == 0) g_esq[c] = v;
    }
    if (tid < 64) {
        int kk = tid >> 3, ch = tid & 7;
        int nc = c >> 7, m = c & 127;
        const float* src = es + kk * 64 + ch * 8;
        uint32_t hp[4];
#pragma unroll
        for (int i = 0; i < 4; i++) hp[i] = pack_hi(src[2*i], src[2*i+1]);
        uint32_t off = (uint32_t)m * 128 + ((uint32_t)(ch ^ (m & 7)) << 4);
        *(uint4*)(g_B + (size_t)(nc * 8 + kk) * 16384 + off) =
            make_uint4(hp[0], hp[1], hp[2], hp[3]);
    }
}

// ---------------------------------------------------------------------------
__global__ __launch_bounds__(256)
void prep_A_kernel(const float* __restrict__ x) {
    __shared__ float s[64 * 65];
    int tile = blockIdx.x >> 3, kk = blockIdx.x & 7;
    int b = tile >> 6, t0 = (tile & 63) * 64;
    int tid = threadIdx.x;
#pragma unroll
    for (int i = 0; i < 16; i++) {
        int idx = i * 256 + tid;
        int k = idx >> 6, m = idx & 63;
        s[k * 65 + m] = x[((size_t)(b * DTOT + kk * 64 + k)) * TT + t0 + m];
    }
    __syncthreads();
    size_t base = (size_t)blockIdx.x * 8192;
    for (int q = tid; q < 512; q += 256) {
        int m = q >> 3, c = q & 7;
        uint32_t hp[4];
#pragma unroll
        for (int i = 0; i < 4; i++)
            hp[i] = pack_hi(s[(c * 8 + 2*i) * 65 + m], s[(c * 8 + 2*i + 1) * 65 + m]);
        uint32_t off = (uint32_t)m * 128 + ((uint32_t)(c ^ (m & 7)) << 4);
        *(uint4*)(g_A + base + off) = make_uint4(hp[0], hp[1], hp[2], hp[3]);
    }
}

// ---------------------------------------------------------------------------
// coarse: EXACT R7 configuration (tid==0 refill, warp tile 32x32, NSLOT=4)
// ---------------------------------------------------------------------------
__global__ __launch_bounds__(256, 2)
void coarse_kernel() {
    extern __shared__ unsigned char dynraw[];
    __shared__ __align__(8) unsigned long long bars[2 * NSLOT];

    uint32_t raw = smem_u32(dynraw);
    uint32_t abase = (raw + 1023u) & ~1023u;
    float* esq_s = (float*)(dynraw + (abase - raw) + ESQ_OFF);
    uint32_t barF[NSLOT], barE[NSLOT];
#pragma unroll
    for (int i = 0; i < NSLOT; i++) {
        barF[i] = smem_u32(&bars[i]);
        barE[i] = smem_u32(&bars[NSLOT + i]);
    }

    int tid = threadIdx.x;
    int lane = tid & 31;
    int wid = tid >> 5;
    int warpM = wid >> 2, warpN = wid & 3;     // 2(M) x 4(N), warp 32x32
    int tile = blockIdx.x;

    if (tid == 0) {
#pragma unroll
        for (int i = 0; i < NSLOT; i++) { mbar_init(barF[i], 1); mbar_init(barE[i], 8); }
    }
    for (int i = tid; i < SEM_SIZEV; i += 256) esq_s[i] = g_esq[i];
    __syncthreads();

    const unsigned char* srcA = g_A + (size_t)tile * (8 * 8192);

    if (tid == 0) {
#pragma unroll
        for (int s = 0; s < NSLOT; s++) {
            mbar_expect_tx(barF[s], SLOT_BYTES);
            bulk_g2s(abase + s * SLOT_BYTES, srcA + (size_t)s * 8192, 8192, barF[s]);
            bulk_g2s(abase + s * SLOT_BYTES + 8192, g_B + (size_t)s * 16384, 16384, barF[s]);
        }
    }

    uint32_t sw = lane & 7;
    uint32_t aRowOff = (uint32_t)(warpM * 32 + (lane & 15)) * 128;
    uint32_t aAdd = lane >> 4;
    uint32_t bRowOff = (uint32_t)(warpN * 32 + (lane & 7) + ((lane & 16) >> 1)) * 128;
    uint32_t bAdd = (lane >> 3) & 1;
    uint32_t caOff[4], cbOff[4];
#pragma unroll
    for (int j = 0; j < 4; j++) {
        caOff[j] = aRowOff + (uint32_t)(((2 * j + aAdd) ^ sw) << 4);
        cbOff[j] = 8192u + bRowOff + (uint32_t)(((2 * j + bAdd) ^ sw) << 4);
    }

    float tV[2][2][2];
    int   tI[2][2][2];
#pragma unroll
    for (int mi = 0; mi < 2; mi++)
#pragma unroll
        for (int h = 0; h < 2; h++) {
            tV[mi][h][0] = tV[mi][h][1] = 3.4e38f;
            tI[mi][h][0] = tI[mi][h][1] = 0;
        }

    for (int nc = 0; nc < NC_COUNT; nc++) {
        float acc[2][4][4];
#pragma unroll
        for (int mi = 0; mi < 2; mi++)
#pragma unroll
            for (int nf = 0; nf < 4; nf++)
#pragma unroll
                for (int e = 0; e < 4; e++) acc[mi][nf][e] = 0.0f;

#pragma unroll
        for (int kk = 0; kk < KK_COUNT; kk++) {
            int s = nc * 8 + kk;
            int slot = kk & 3;
            uint32_t p = (uint32_t)(((nc << 1) + (kk >> 2)) & 1);
            mbar_wait(barF[slot], p);
            uint32_t sb = abase + slot * SLOT_BYTES;

#pragma unroll
            for (int j = 0; j < 4; j++) {
                uint32_t ar[2][4], br[2][4];
#pragma unroll
                for (int mi = 0; mi < 2; mi++)
                    LDSM4(ar[mi][0], ar[mi][1], ar[mi][2], ar[mi][3],
                          sb + caOff[j] + mi * 2048);
#pragma unroll
                for (int nf2 = 0; nf2 < 2; nf2++)
                    LDSM4(br[nf2][0], br[nf2][1], br[nf2][2], br[nf2][3],
                          sb + cbOff[j] + nf2 * 2048);
#pragma unroll
                for (int mi = 0; mi < 2; mi++)
#pragma unroll
                    for (int nf2 = 0; nf2 < 2; nf2++) {
                        MMA16816(acc[mi][2 * nf2],     ar[mi][0], ar[mi][1], ar[mi][2], ar[mi][3],
                                 br[nf2][0], br[nf2][1]);
                        MMA16816(acc[mi][2 * nf2 + 1], ar[mi][0], ar[mi][1], ar[mi][2], ar[mi][3],
                                 br[nf2][2], br[nf2][3]);
                    }
            }
            if (lane == 0) mbar_arrive(barE[slot]);

            if (tid == 0 && s + NSLOT < NC_COUNT * KK_COUNT) {
                mbar_wait(barE[slot], p);
                int s2 = s + NSLOT;
                int nc2 = s2 >> 3, kk2 = s2 & 7;
                mbar_expect_tx(barF[slot], SLOT_BYTES);
                bulk_g2s(sb, srcA + (size_t)kk2 * 8192, 8192, barF[slot]);
                bulk_g2s(sb + 8192, g_B + (size_t)(nc2 * 8 + kk2) * 16384, 16384, barF[slot]);
            }
        }

        int cbase = nc * 128 + warpN * 32 + (lane & 3) * 2;
#pragma unroll
        for (int nf = 0; nf < 4; nf++) {
            float eq0 = esq_s[cbase + nf * 8 + 0];
            float eq1 = esq_s[cbase + nf * 8 + 1];
            int c0 = cbase + nf * 8, c1 = c0 + 1;
#pragma unroll
            for (int mi = 0; mi < 2; mi++) {
                top2_ins(eq0 - 2.0f * acc[mi][nf][0], c0, tV[mi][0], tI[mi][0]);
                top2_ins(eq1 - 2.0f * acc[mi][nf][1], c1, tV[mi][0], tI[mi][0]);
                top2_ins(eq0 - 2.0f * acc[mi][nf][2], c0, tV[mi][1], tI[mi][1]);
                top2_ins(eq1 - 2.0f * acc[mi][nf][3], c1, tV[mi][1], tI[mi][1]);
            }
        }
    }

    int slotIdx = (warpN * 4 + (lane & 3)) * 2;
#pragma unroll
    for (int mi = 0; mi < 2; mi++)
#pragma unroll
        for (int h = 0; h < 2; h++) {
            int r = tile * 64 + warpM * 32 + mi * 16 + h * 8 + (lane >> 2);
            size_t base = (size_t)r * 32 + slotIdx;
            g_candV[base]     = tV[mi][h][0];
            g_candV[base + 1] = tV[mi][h][1];
            g_candI[base]     = tI[mi][h][0];
            g_candI[base + 1] = tI[mi][h][1];
        }
}

// ---------------------------------------------------------------------------
// rescore: R7 structure + 2-way unrolled candidate loop (bitwise-identical math)
// ---------------------------------------------------------------------------
#define XS_PITCH 513
#define DYN_RESCORE (32 * XS_PITCH * 4)

__global__ __launch_bounds__(1024)
void rescore_kernel(const float* __restrict__ x,
                    const float* __restrict__ probs_sem,
                    float* __restrict__ outq,
                    float* __restrict__ outc) {
    extern __shared__ float xs[];
    __shared__ int codes_s[32];

    int tid = threadIdx.x;
    int lane = tid & 31;
    int w = tid >> 5;
    int b = blockIdx.x >> 7;
    int t0 = (blockIdx.x & 127) * 32;

    const float* xb = x + (size_t)b * DTOT * TT + t0;

#pragma unroll
    for (int it = 0; it < 16; it++) {
        int idx = it * 1024 + tid;
        int d = idx >> 5, t = idx & 31;
        xs[t * XS_PITCH + d] = xb[(size_t)d * TT + t];
    }
    __syncthreads();

    int r = blockIdx.x * 32 + w;
    float candV = g_candV[(size_t)r * 32 + lane];
    int   candI = g_candI[(size_t)r * 32 + lane];
    float candE = g_esq[candI];

    float xsq = 0.0f;
#pragma unroll
    for (int i = 0; i < 16; i++) {
        float v = xs[w * XS_PITCH + i * 32 + lane];
        xsq += v * v;
    }
#pragma unroll
    for (int o = 16; o > 0; o >>= 1) xsq += __shfl_xor_sync(0xffffffffu, xsq, o);

    float delta = DELTA_C * sqrtf(xsq * candE);
    float ub = candV + delta;
#pragma unroll
    for (int o = 16; o > 0; o >>= 1) ub = fminf(ub, __shfl_xor_sync(0xffffffffu, ub, o));
    unsigned pm = __ballot_sync(0xffffffffu, candV - delta <= ub);

    float bestd = 3.4e38f;
    int bestc = SEM_SIZEV;
    while (pm) {
        int p0 = __ffs(pm) - 1;
        pm &= pm - 1;
        int has2 = (pm != 0u);
        int p1 = has2 ? (__ffs(pm) - 1) : p0;
        if (has2) pm &= pm - 1;

        int   c0 = __shfl_sync(0xffffffffu, candI, p0);
        float e0 = __shfl_sync(0xffffffffu, candE, p0);
        int   c1 = __shfl_sync(0xffffffffu, candI, p1);
        float e1 = __shfl_sync(0xffffffffu, candE, p1);
        const float* er0 = g_emb + (size_t)c0 * SEM_DIMV;
        const float* er1 = g_emb + (size_t)c1 * SEM_DIMV;
        float dot0 = 0.0f, dot1 = 0.0f;
#pragma unroll
        for (int i = 0; i < 16; i++) {
            float xv = xs[w * XS_PITCH + i * 32 + lane];
            dot0 += xv * er0[i * 32 + lane];
            dot1 += xv * er1[i * 32 + lane];
        }
#pragma unroll
        for (int o = 16; o > 0; o >>= 1) {
            dot0 += __shfl_xor_sync(0xffffffffu, dot0, o);
            dot1 += __shfl_xor_sync(0xffffffffu, dot1, o);
        }
        float d0 = e0 - 2.0f * dot0;
        if (d0 < bestd || (d0 == bestd && c0 < bestc)) { bestd = d0; bestc = c0; }
        if (has2) {
            float d1 = e1 - 2.0f * dot1;
            if (d1 < bestd || (d1 == bestd && c1 < bestc)) { bestd = d1; bestc = c1; }
        }
    }
    if (lane == 0) {
        codes_s[w] = bestc;
        outc[(size_t)b * 33 * TT + t0 + w] = (float)bestc;
    }
    __syncthreads();

    float psem = probs_sem[b];
    float* outqb = outq + (size_t)b * DTOT * TT + t0;
    if (psem < 0.5f) {
        int c = codes_s[w];
        const float* er = g_emb + (size_t)c * SEM_DIMV;
        __syncthreads();
#pragma unroll
        for (int i = 0; i < 16; i++)
            xs[w * XS_PITCH + i * 32 + lane] = er[i * 32 + lane];
        __syncthreads();
    }
#pragma unroll
    for (int it = 0; it < 16; it++) {
        int idx = it * 1024 + tid;
        int d = idx >> 5, t = idx & 31;
        outqb[(size_t)d * TT + t] = xs[t * XS_PITCH + d];
    }
}

// ---------------------------------------------------------------------------
__global__ void aco_kernel(const float* __restrict__ x,
                           const float* __restrict__ noise,
                           const float* __restrict__ probs_aco,
                           float* __restrict__ outq,
                           float* __restrict__ outc) {
    int idx = blockIdx.x * blockDim.x + threadIdx.x;
    int t = idx & 4095;
    int rj = idx >> 12;
    int b = rj >> 5, j = rj & 31;

    float a = x[((size_t)b * DTOT + SEM_DIMV + j) * TT + t];
    float zb = tanhf(a) * HALFV;
    float pa = probs_aco[b];
    float zout;
    if (pa < 0.5f) {
        zout = rintf(zb);
    } else if (pa < 0.75f) {
        float ns = (noise[(size_t)rj * TT + t] * 2.0f - 1.0f) * (HALFV / 9.0f);
        zout = fminf(fmaxf(zb + ns, -HALFV), HALFV);
    } else {
        zout = zb;
    }
    float code = fminf(fmaxf(rintf(zout + HALFV), 0.0f), 8.0f);
    outq[((size_t)b * DTOT + SEM_DIMV + j) * TT + t] = zout * 0.25f;
    outc[((size_t)b * 33 + 1 + j) * TT + t] = code;
}

// ---------------------------------------------------------------------------
extern "C" void kernel_launch(void* const* d_in, const int* in_sizes, int n_in,
                              void* d_out, int out_size) {
    const float* x     = (const float*)d_in[0];
    const float* esum  = (const float*)d_in[1];
    const float* usage = (const float*)d_in[2];
    const float* noise = (const float*)d_in[3];
    const float* psem  = (const float*)d_in[4];
    const float* paco  = (const float*)d_in[5];

    float* outq = (float*)d_out;
    float* outc = outq + (size_t)BB * DTOT * TT;

    cudaFuncSetAttribute(coarse_kernel,
                         cudaFuncAttributeMaxDynamicSharedMemorySize, DYN_BYTES);
    cudaFuncSetAttribute(rescore_kernel,
                         cudaFuncAttributeMaxDynamicSharedMemorySize, DYN_RESCORE);

    prep_embB_kernel<<<SEM_SIZEV, 128>>>(esum, usage);
    prep_A_kernel<<<N_TILES * 8, 256>>>(x);
    coarse_kernel<<<N_TILES, 256, DYN_BYTES>>>();
    rescore_kernel<<<NROWS / 32, 1024, DYN_RESCORE>>>(x, psem, outq, outc);
    aco_kernel<<<(BB * ACO_DIMV * TT) / 256, 256>>>(x, noise, paco, outq, outc);
}

// round 12
// speedup vs baseline: 1.1758x; 1.0007x over previous
#include <cuda_runtime.h>
#include <cuda_bf16.h>
#include <cstdint>

#define SEM_DIMV 512
#define SEM_SIZEV 2048
#define ACO_DIMV 32
#define BB 16
#define TT 4096
#define NROWS (BB*TT)
#define DTOT 544
#define HALFV 4.0f
#define EPSV 1e-5f

#define TILE_M 64
#define N_TILES (NROWS/TILE_M)   // 1024
#define NC_COUNT 16              // 16 chunks of 128 codes
#define KK_COUNT 8
#define NSLOT 4
// slot: A hi 8KB @0, B hi 16KB @8192  -> 24KB
#define SLOT_BYTES 24576
#define ESQ_OFF (NSLOT*SLOT_BYTES)              // 98304
#define DYN_BYTES (ESQ_OFF + 8192 + 1024)       // ~105KB -> 2 CTAs/SM
#define DELTA_C 0.0088f

__device__ __align__(128) unsigned char g_A[N_TILES * 8 * 8192];   // 64MB
__device__ __align__(128) unsigned char g_B[128 * 16384];          // 2MB
__device__ float g_emb[SEM_SIZEV * SEM_DIMV];
__device__ float g_esq[SEM_SIZEV];
__device__ float g_candV[(size_t)NROWS * 32];                      // 8MB
__device__ int   g_candI[(size_t)NROWS * 32];                      // 8MB

// ------------------------------------------------------------------ helpers
__device__ __forceinline__ uint32_t smem_u32(const void* p) {
    uint32_t a;
    asm("{ .reg .u64 t; cvta.to.shared.u64 t, %1; cvt.u32.u64 %0, t; }" : "=r"(a) : "l"(p));
    return a;
}
__device__ __forceinline__ void mbar_init(uint32_t a, uint32_t cnt) {
    asm volatile("mbarrier.init.shared.b64 [%0], %1;" :: "r"(a), "r"(cnt) : "memory");
}
__device__ __forceinline__ void mbar_expect_tx(uint32_t a, uint32_t bytes) {
    asm volatile("mbarrier.arrive.expect_tx.shared.b64 _, [%0], %1;" :: "r"(a), "r"(bytes) : "memory");
}
__device__ __forceinline__ void mbar_arrive(uint32_t a) {
    asm volatile("mbarrier.arrive.shared.b64 _, [%0];" :: "r"(a) : "memory");
}
__device__ __forceinline__ void mbar_wait(uint32_t a, uint32_t parity) {
    asm volatile(
        "{\n\t.reg .pred P;\n\t"
        "W_%=:\n\t"
        "mbarrier.try_wait.parity.acquire.cta.shared::cta.b64 P, [%0], %1, 0x989680;\n\t"
        "@!P bra W_%=;\n\t}"
        :: "r"(a), "r"(parity) : "memory");
}
__device__ __forceinline__ void bulk_g2s(uint32_t dst, const void* src, uint32_t bytes, uint32_t mbar) {
    asm volatile("cp.async.bulk.shared::cluster.global.mbarrier::complete_tx::bytes [%0], [%1], %2, [%3];"
        :: "r"(dst), "l"(src), "r"(bytes), "r"(mbar) : "memory");
}

#define LDSM4(R0,R1,R2,R3,ADDR) \
    asm volatile("ldmatrix.sync.aligned.m8n8.x4.shared.b16 {%0,%1,%2,%3}, [%4];" \
        : "=r"(R0), "=r"(R1), "=r"(R2), "=r"(R3) : "r"(ADDR))

#define MMA16816(D, A0,A1,A2,A3, B0,B1) \
    asm volatile("mma.sync.aligned.m16n8k16.row.col.f32.bf16.bf16.f32 " \
        "{%0,%1,%2,%3},{%4,%5,%6,%7},{%8,%9},{%0,%1,%2,%3};" \
        : "+f"((D)[0]), "+f"((D)[1]), "+f"((D)[2]), "+f"((D)[3]) \
        : "r"(A0), "r"(A1), "r"(A2), "r"(A3), "r"(B0), "r"(B1))

__device__ __forceinline__ uint32_t pack_hi(float f0, float f1) {
    __nv_bfloat16 h0 = __float2bfloat16(f0);
    __nv_bfloat16 h1 = __float2bfloat16(f1);
    return (uint32_t)__bfloat16_as_ushort(h0) | ((uint32_t)__bfloat16_as_ushort(h1) << 16);
}
__device__ __forceinline__ void top2_ins(float v, int i, float* V, int* I) {
    if (v < V[0]) { V[1] = V[0]; I[1] = I[0]; V[0] = v; I[0] = i; }
    else if (v < V[1]) { V[1] = v; I[1] = i; }
}

// ---------------------------------------------------------------------------
// prep_embB: fused emb normalize + |e|^2 + swizzled bf16 codebook tiles
// ---------------------------------------------------------------------------
__global__ void prep_embB_kernel(const float* __restrict__ esum,
                                 const float* __restrict__ usage) {
    __shared__ float es[SEM_DIMV];
    __shared__ float red[128];
    int c = blockIdx.x, tid = threadIdx.x;
    float inv = 1.0f / fmaxf(usage[c], EPSV);
    float acc = 0.0f;
#pragma unroll
    for (int i = 0; i < 4; i++) {
        int d = tid + i * 128;
        float e = esum[c * SEM_DIMV + d] * inv;
        g_emb[c * SEM_DIMV + d] = e;
        es[d] = e;
        acc += e * e;
    }
    red[tid] = acc;
    __syncthreads();
    if (tid < 64) red[tid] += red[tid + 64];
    __syncthreads();
    if (tid < 32) {
        float v = red[tid] + red[tid + 32];
#pragma unroll
        for (int o = 16; o > 0; o >>= 1) v += __shfl_down_sync(0xffffffffu, v, o);
        if (tid == 0) g_esq[c] = v;
    }
    if (tid < 64) {
        int kk = tid >> 3, ch = tid & 7;
        int nc = c >> 7, m = c & 127;
        const float* src = es + kk * 64 + ch * 8;
        uint32_t hp[4];
#pragma unroll
        for (int i = 0; i < 4; i++) hp[i] = pack_hi(src[2*i], src[2*i+1]);
        uint32_t off = (uint32_t)m * 128 + ((uint32_t)(ch ^ (m & 7)) << 4);
        *(uint4*)(g_B + (size_t)(nc * 8 + kk) * 16384 + off) =
            make_uint4(hp[0], hp[1], hp[2], hp[3]);
    }
}

// ---------------------------------------------------------------------------
__global__ __launch_bounds__(256)
void prep_A_kernel(const float* __restrict__ x) {
    __shared__ float s[64 * 65];
    int tile = blockIdx.x >> 3, kk = blockIdx.x & 7;
    int b = tile >> 6, t0 = (tile & 63) * 64;
    int tid = threadIdx.x;
#pragma unroll
    for (int i = 0; i < 16; i++) {
        int idx = i * 256 + tid;
        int k = idx >> 6, m = idx & 63;
        s[k * 65 + m] = x[((size_t)(b * DTOT + kk * 64 + k)) * TT + t0 + m];
    }
    __syncthreads();
    size_t base = (size_t)blockIdx.x * 8192;
    for (int q = tid; q < 512; q += 256) {
        int m = q >> 3, c = q & 7;
        uint32_t hp[4];
#pragma unroll
        for (int i = 0; i < 4; i++)
            hp[i] = pack_hi(s[(c * 8 + 2*i) * 65 + m], s[(c * 8 + 2*i + 1) * 65 + m]);
        uint32_t off = (uint32_t)m * 128 + ((uint32_t)(c ^ (m & 7)) << 4);
        *(uint4*)(g_A + base + off) = make_uint4(hp[0], hp[1], hp[2], hp[3]);
    }
}

// ---------------------------------------------------------------------------
// coarse: EXACT R10/R7 configuration (tid==0 refill, warp tile 32x32, NSLOT=4)
// ---------------------------------------------------------------------------
__global__ __launch_bounds__(256, 2)
void coarse_kernel() {
    extern __shared__ unsigned char dynraw[];
    __shared__ __align__(8) unsigned long long bars[2 * NSLOT];

    uint32_t raw = smem_u32(dynraw);
    uint32_t abase = (raw + 1023u) & ~1023u;
    float* esq_s = (float*)(dynraw + (abase - raw) + ESQ_OFF);
    uint32_t barF[NSLOT], barE[NSLOT];
#pragma unroll
    for (int i = 0; i < NSLOT; i++) {
        barF[i] = smem_u32(&bars[i]);
        barE[i] = smem_u32(&bars[NSLOT + i]);
    }

    int tid = threadIdx.x;
    int lane = tid & 31;
    int wid = tid >> 5;
    int warpM = wid >> 2, warpN = wid & 3;     // 2(M) x 4(N), warp 32x32
    int tile = blockIdx.x;

    if (tid == 0) {
#pragma unroll
        for (int i = 0; i < NSLOT; i++) { mbar_init(barF[i], 1); mbar_init(barE[i], 8); }
    }
    for (int i = tid; i < SEM_SIZEV; i += 256) esq_s[i] = g_esq[i];
    __syncthreads();

    const unsigned char* srcA = g_A + (size_t)tile * (8 * 8192);

    if (tid == 0) {
#pragma unroll
        for (int s = 0; s < NSLOT; s++) {
            mbar_expect_tx(barF[s], SLOT_BYTES);
            bulk_g2s(abase + s * SLOT_BYTES, srcA + (size_t)s * 8192, 8192, barF[s]);
            bulk_g2s(abase + s * SLOT_BYTES + 8192, g_B + (size_t)s * 16384, 16384, barF[s]);
        }
    }

    uint32_t sw = lane & 7;
    uint32_t aRowOff = (uint32_t)(warpM * 32 + (lane & 15)) * 128;
    uint32_t aAdd = lane >> 4;
    uint32_t bRowOff = (uint32_t)(warpN * 32 + (lane & 7) + ((lane & 16) >> 1)) * 128;
    uint32_t bAdd = (lane >> 3) & 1;
    uint32_t caOff[4], cbOff[4];
#pragma unroll
    for (int j = 0; j < 4; j++) {
        caOff[j] = aRowOff + (uint32_t)(((2 * j + aAdd) ^ sw) << 4);
        cbOff[j] = 8192u + bRowOff + (uint32_t)(((2 * j + bAdd) ^ sw) << 4);
    }

    float tV[2][2][2];
    int   tI[2][2][2];
#pragma unroll
    for (int mi = 0; mi < 2; mi++)
#pragma unroll
        for (int h = 0; h < 2; h++) {
            tV[mi][h][0] = tV[mi][h][1] = 3.4e38f;
            tI[mi][h][0] = tI[mi][h][1] = 0;
        }

    for (int nc = 0; nc < NC_COUNT; nc++) {
        float acc[2][4][4];
#pragma unroll
        for (int mi = 0; mi < 2; mi++)
#pragma unroll
            for (int nf = 0; nf < 4; nf++)
#pragma unroll
                for (int e = 0; e < 4; e++) acc[mi][nf][e] = 0.0f;

#pragma unroll
        for (int kk = 0; kk < KK_COUNT; kk++) {
            int s = nc * 8 + kk;
            int slot = kk & 3;
            uint32_t p = (uint32_t)(((nc << 1) + (kk >> 2)) & 1);
            mbar_wait(barF[slot], p);
            uint32_t sb = abase + slot * SLOT_BYTES;

#pragma unroll
            for (int j = 0; j < 4; j++) {
                uint32_t ar[2][4], br[2][4];
#pragma unroll
                for (int mi = 0; mi < 2; mi++)
                    LDSM4(ar[mi][0], ar[mi][1], ar[mi][2], ar[mi][3],
                          sb + caOff[j] + mi * 2048);
#pragma unroll
                for (int nf2 = 0; nf2 < 2; nf2++)
                    LDSM4(br[nf2][0], br[nf2][1], br[nf2][2], br[nf2][3],
                          sb + cbOff[j] + nf2 * 2048);
#pragma unroll
                for (int mi = 0; mi < 2; mi++)
#pragma unroll
                    for (int nf2 = 0; nf2 < 2; nf2++) {
                        MMA16816(acc[mi][2 * nf2],     ar[mi][0], ar[mi][1], ar[mi][2], ar[mi][3],
                                 br[nf2][0], br[nf2][1]);
                        MMA16816(acc[mi][2 * nf2 + 1], ar[mi][0], ar[mi][1], ar[mi][2], ar[mi][3],
                                 br[nf2][2], br[nf2][3]);
                    }
            }
            if (lane == 0) mbar_arrive(barE[slot]);

            if (tid == 0 && s + NSLOT < NC_COUNT * KK_COUNT) {
                mbar_wait(barE[slot], p);
                int s2 = s + NSLOT;
                int nc2 = s2 >> 3, kk2 = s2 & 7;
                mbar_expect_tx(barF[slot], SLOT_BYTES);
                bulk_g2s(sb, srcA + (size_t)kk2 * 8192, 8192, barF[slot]);
                bulk_g2s(sb + 8192, g_B + (size_t)(nc2 * 8 + kk2) * 16384, 16384, barF[slot]);
            }
        }

        int cbase = nc * 128 + warpN * 32 + (lane & 3) * 2;
#pragma unroll
        for (int nf = 0; nf < 4; nf++) {
            float eq0 = esq_s[cbase + nf * 8 + 0];
            float eq1 = esq_s[cbase + nf * 8 + 1];
            int c0 = cbase + nf * 8, c1 = c0 + 1;
#pragma unroll
            for (int mi = 0; mi < 2; mi++) {
                top2_ins(eq0 - 2.0f * acc[mi][nf][0], c0, tV[mi][0], tI[mi][0]);
                top2_ins(eq1 - 2.0f * acc[mi][nf][1], c1, tV[mi][0], tI[mi][0]);
                top2_ins(eq0 - 2.0f * acc[mi][nf][2], c0, tV[mi][1], tI[mi][1]);
                top2_ins(eq1 - 2.0f * acc[mi][nf][3], c1, tV[mi][1], tI[mi][1]);
            }
        }
    }

    int slotIdx = (warpN * 4 + (lane & 3)) * 2;
#pragma unroll
    for (int mi = 0; mi < 2; mi++)
#pragma unroll
        for (int h = 0; h < 2; h++) {
            int r = tile * 64 + warpM * 32 + mi * 16 + h * 8 + (lane >> 2);
            size_t base = (size_t)r * 32 + slotIdx;
            g_candV[base]     = tV[mi][h][0];
            g_candV[base + 1] = tV[mi][h][1];
            g_candI[base]     = tI[mi][h][0];
            g_candI[base + 1] = tI[mi][h][1];
        }
}

// ---------------------------------------------------------------------------
// rescore: R10 + single-survivor fast path (provably exact)
// ---------------------------------------------------------------------------
#define XS_PITCH 513
#define DYN_RESCORE (32 * XS_PITCH * 4)

__global__ __launch_bounds__(1024)
void rescore_kernel(const float* __restrict__ x,
                    const float* __restrict__ probs_sem,
                    float* __restrict__ outq,
                    float* __restrict__ outc) {
    extern __shared__ float xs[];
    __shared__ int codes_s[32];

    int tid = threadIdx.x;
    int lane = tid & 31;
    int w = tid >> 5;
    int b = blockIdx.x >> 7;
    int t0 = (blockIdx.x & 127) * 32;

    const float* xb = x + (size_t)b * DTOT * TT + t0;

#pragma unroll
    for (int it = 0; it < 16; it++) {
        int idx = it * 1024 + tid;
        int d = idx >> 5, t = idx & 31;
        xs[t * XS_PITCH + d] = xb[(size_t)d * TT + t];
    }
    __syncthreads();

    int r = blockIdx.x * 32 + w;
    float candV = g_candV[(size_t)r * 32 + lane];
    int   candI = g_candI[(size_t)r * 32 + lane];
    float candE = g_esq[candI];

    float xsq = 0.0f;
#pragma unroll
    for (int i = 0; i < 16; i++) {
        float v = xs[w * XS_PITCH + i * 32 + lane];
        xsq += v * v;
    }
#pragma unroll
    for (int o = 16; o > 0; o >>= 1) xsq += __shfl_xor_sync(0xffffffffu, xsq, o);

    float delta = DELTA_C * sqrtf(xsq * candE);
    float ub = candV + delta;
#pragma unroll
    for (int o = 16; o > 0; o >>= 1) ub = fminf(ub, __shfl_xor_sync(0xffffffffu, ub, o));
    unsigned pm = __ballot_sync(0xffffffffu, candV - delta <= ub);

    int bestc;
    if (__popc(pm) == 1) {
        // exactly one survivor: it is provably the exact argmin — no rescoring
        bestc = __shfl_sync(0xffffffffu, candI, __ffs(pm) - 1);
    } else {
        float bestd = 3.4e38f;
        bestc = SEM_SIZEV;
        while (pm) {
            int p0 = __ffs(pm) - 1;
            pm &= pm - 1;
            int has2 = (pm != 0u);
            int p1 = has2 ? (__ffs(pm) - 1) : p0;
            if (has2) pm &= pm - 1;

            int   c0 = __shfl_sync(0xffffffffu, candI, p0);
            float e0 = __shfl_sync(0xffffffffu, candE, p0);
            int   c1 = __shfl_sync(0xffffffffu, candI, p1);
            float e1 = __shfl_sync(0xffffffffu, candE, p1);
            const float* er0 = g_emb + (size_t)c0 * SEM_DIMV;
            const float* er1 = g_emb + (size_t)c1 * SEM_DIMV;
            float dot0 = 0.0f, dot1 = 0.0f;
#pragma unroll
            for (int i = 0; i < 16; i++) {
                float xv = xs[w * XS_PITCH + i * 32 + lane];
                dot0 += xv * er0[i * 32 + lane];
                dot1 += xv * er1[i * 32 + lane];
            }
#pragma unroll
            for (int o = 16; o > 0; o >>= 1) {
                dot0 += __shfl_xor_sync(0xffffffffu, dot0, o);
                dot1 += __shfl_xor_sync(0xffffffffu, dot1, o);
            }
            float d0 = e0 - 2.0f * dot0;
            if (d0 < bestd || (d0 == bestd && c0 < bestc)) { bestd = d0; bestc = c0; }
            if (has2) {
                float d1 = e1 - 2.0f * dot1;
                if (d1 < bestd || (d1 == bestd && c1 < bestc)) { bestd = d1; bestc = c1; }
            }
        }
    }
    if (lane == 0) {
        codes_s[w] = bestc;
        outc[(size_t)b * 33 * TT + t0 + w] = (float)bestc;
    }
    __syncthreads();

    float psem = probs_sem[b];
    float* outqb = outq + (size_t)b * DTOT * TT + t0;
    if (psem < 0.5f) {
        int c = codes_s[w];
        const float* er = g_emb + (size_t)c * SEM_DIMV;
        __syncthreads();
#pragma unroll
        for (int i = 0; i < 16; i++)
            xs[w * XS_PITCH + i * 32 + lane] = er[i * 32 + lane];
        __syncthreads();
    }
#pragma unroll
    for (int it = 0; it < 16; it++) {
        int idx = it * 1024 + tid;
        int d = idx >> 5, t = idx & 31;
        outqb[(size_t)d * TT + t] = xs[t * XS_PITCH + d];
    }
}

// ---------------------------------------------------------------------------
__global__ void aco_kernel(const float* __restrict__ x,
                           const float* __restrict__ noise,
                           const float* __restrict__ probs_aco,
                           float* __restrict__ outq,
                           float* __restrict__ outc) {
    int idx = blockIdx.x * blockDim.x + threadIdx.x;
    int t = idx & 4095;
    int rj = idx >> 12;
    int b = rj >> 5, j = rj & 31;

    float a = x[((size_t)b * DTOT + SEM_DIMV + j) * TT + t];
    float zb = tanhf(a) * HALFV;
    float pa = probs_aco[b];
    float zout;
    if (pa < 0.5f) {
        zout = rintf(zb);
    } else if (pa < 0.75f) {
        float ns = (noise[(size_t)rj * TT + t] * 2.0f - 1.0f) * (HALFV / 9.0f);
        zout = fminf(fmaxf(zb + ns, -HALFV), HALFV);
    } else {
        zout = zb;
    }
    float code = fminf(fmaxf(rintf(zout + HALFV), 0.0f), 8.0f);
    outq[((size_t)b * DTOT + SEM_DIMV + j) * TT + t] = zout * 0.25f;
    outc[((size_t)b * 33 + 1 + j) * TT + t] = code;
}

// ---------------------------------------------------------------------------
extern "C" void kernel_launch(void* const* d_in, const int* in_sizes, int n_in,
                              void* d_out, int out_size) {
    const float* x     = (const float*)d_in[0];
    const float* esum  = (const float*)d_in[1];
    const float* usage = (const float*)d_in[2];
    const float* noise = (const float*)d_in[3];
    const float* psem  = (const float*)d_in[4];
    const float* paco  = (const float*)d_in[5];

    float* outq = (float*)d_out;
    float* outc = outq + (size_t)BB * DTOT * TT;

    cudaFuncSetAttribute(coarse_kernel,
                         cudaFuncAttributeMaxDynamicSharedMemorySize, DYN_BYTES);
    cudaFuncSetAttribute(rescore_kernel,
                         cudaFuncAttributeMaxDynamicSharedMemorySize, DYN_RESCORE);

    prep_embB_kernel<<<SEM_SIZEV, 128>>>(esum, usage);
    prep_A_kernel<<<N_TILES * 8, 256>>>(x);
    coarse_kernel<<<N_TILES, 256, DYN_BYTES>>>();
    rescore_kernel<<<NROWS / 32, 1024, DYN_RESCORE>>>(x, psem, outq, outc);
    aco_kernel<<<(BB * ACO_DIMV * TT) / 256, 256>>>(x, noise, paco, outq, outc);
}

// round 13
// speedup vs baseline: 1.1968x; 1.0178x over previous
#include <cuda_runtime.h>
#include <cuda_bf16.h>
#include <cstdint>

#define SEM_DIMV 512
#define SEM_SIZEV 2048
#define ACO_DIMV 32
#define BB 16
#define TT 4096
#define NROWS (BB*TT)
#define DTOT 544
#define HALFV 4.0f
#define EPSV 1e-5f

#define TILE_M 64
#define N_TILES (NROWS/TILE_M)   // 1024
#define NC_COUNT 16              // 16 chunks of 128 codes
#define KK_COUNT 8
#define NSLOT 4
// slot: A hi 8KB @0, B hi 16KB @8192  -> 24KB
#define SLOT_BYTES 24576
#define ESQ_OFF (NSLOT*SLOT_BYTES)              // 98304
#define DYN_BYTES (ESQ_OFF + 8192 + 1024)       // ~105KB -> 2 CTAs/SM
#define DELTA_C 0.0088f

__device__ __align__(128) unsigned char g_A[N_TILES * 8 * 8192];   // 64MB
__device__ __align__(128) unsigned char g_B[128 * 16384];          // 2MB
__device__ float g_emb[SEM_SIZEV * SEM_DIMV];
__device__ float g_esq[SEM_SIZEV];
__device__ float g_candV[(size_t)NROWS * 32];                      // 8MB
__device__ int   g_candI[(size_t)NROWS * 32];                      // 8MB

// ------------------------------------------------------------------ helpers
__device__ __forceinline__ uint32_t smem_u32(const void* p) {
    uint32_t a;
    asm("{ .reg .u64 t; cvta.to.shared.u64 t, %1; cvt.u32.u64 %0, t; }" : "=r"(a) : "l"(p));
    return a;
}
__device__ __forceinline__ void mbar_init(uint32_t a, uint32_t cnt) {
    asm volatile("mbarrier.init.shared.b64 [%0], %1;" :: "r"(a), "r"(cnt) : "memory");
}
__device__ __forceinline__ void mbar_expect_tx(uint32_t a, uint32_t bytes) {
    asm volatile("mbarrier.arrive.expect_tx.shared.b64 _, [%0], %1;" :: "r"(a), "r"(bytes) : "memory");
}
__device__ __forceinline__ void mbar_arrive(uint32_t a) {
    asm volatile("mbarrier.arrive.shared.b64 _, [%0];" :: "r"(a) : "memory");
}
__device__ __forceinline__ void mbar_wait(uint32_t a, uint32_t parity) {
    asm volatile(
        "{\n\t.reg .pred P;\n\t"
        "W_%=:\n\t"
        "mbarrier.try_wait.parity.acquire.cta.shared::cta.b64 P, [%0], %1, 0x989680;\n\t"
        "@!P bra W_%=;\n\t}"
        :: "r"(a), "r"(parity) : "memory");
}
__device__ __forceinline__ void bulk_g2s(uint32_t dst, const void* src, uint32_t bytes, uint32_t mbar) {
    asm volatile("cp.async.bulk.shared::cluster.global.mbarrier::complete_tx::bytes [%0], [%1], %2, [%3];"
        :: "r"(dst), "l"(src), "r"(bytes), "r"(mbar) : "memory");
}

#define LDSM4(R0,R1,R2,R3,ADDR) \
    asm volatile("ldmatrix.sync.aligned.m8n8.x4.shared.b16 {%0,%1,%2,%3}, [%4];" \
        : "=r"(R0), "=r"(R1), "=r"(R2), "=r"(R3) : "r"(ADDR))

#define MMA16816(D, A0,A1,A2,A3, B0,B1) \
    asm volatile("mma.sync.aligned.m16n8k16.row.col.f32.bf16.bf16.f32 " \
        "{%0,%1,%2,%3},{%4,%5,%6,%7},{%8,%9},{%0,%1,%2,%3};" \
        : "+f"((D)[0]), "+f"((D)[1]), "+f"((D)[2]), "+f"((D)[3]) \
        : "r"(A0), "r"(A1), "r"(A2), "r"(A3), "r"(B0), "r"(B1))

__device__ __forceinline__ uint32_t pack_hi(float f0, float f1) {
    __nv_bfloat16 h0 = __float2bfloat16(f0);
    __nv_bfloat16 h1 = __float2bfloat16(f1);
    return (uint32_t)__bfloat16_as_ushort(h0) | ((uint32_t)__bfloat16_as_ushort(h1) << 16);
}
__device__ __forceinline__ void top2_ins(float v, int i, float* V, int* I) {
    if (v < V[0]) { V[1] = V[0]; I[1] = I[0]; V[0] = v; I[0] = i; }
    else if (v < V[1]) { V[1] = v; I[1] = i; }
}

// ---------------------------------------------------------------------------
// prep_embB: fused emb normalize + |e|^2 + swizzled bf16 codebook tiles
// ---------------------------------------------------------------------------
__global__ void prep_embB_kernel(const float* __restrict__ esum,
                                 const float* __restrict__ usage) {
    __shared__ float es[SEM_DIMV];
    __shared__ float red[128];
    int c = blockIdx.x, tid = threadIdx.x;
    float inv = 1.0f / fmaxf(usage[c], EPSV);
    float acc = 0.0f;
#pragma unroll
    for (int i = 0; i < 4; i++) {
        int d = tid + i * 128;
        float e = esum[c * SEM_DIMV + d] * inv;
        g_emb[c * SEM_DIMV + d] = e;
        es[d] = e;
        acc += e * e;
    }
    red[tid] = acc;
    __syncthreads();
    if (tid < 64) red[tid] += red[tid + 64];
    __syncthreads();
    if (tid < 32) {
        float v = red[tid] + red[tid + 32];
#pragma unroll
        for (int o = 16; o > 0; o >>= 1) v += __shfl_down_sync(0xffffffffu, v, o);
        if (tid == 0) g_esq[c] = v;
    }
    if (tid < 64) {
        int kk = tid >> 3, ch = tid & 7;
        int nc = c >> 7, m = c & 127;
        const float* src = es + kk * 64 + ch * 8;
        uint32_t hp[4];
#pragma unroll
        for (int i = 0; i < 4; i++) hp[i] = pack_hi(src[2*i], src[2*i+1]);
        uint32_t off = (uint32_t)m * 128 + ((uint32_t)(ch ^ (m & 7)) << 4);
        *(uint4*)(g_B + (size_t)(nc * 8 + kk) * 16384 + off) =
            make_uint4(hp[0], hp[1], hp[2], hp[3]);
    }
}

// ---------------------------------------------------------------------------
__global__ __launch_bounds__(256)
void prep_A_kernel(const float* __restrict__ x) {
    __shared__ float s[64 * 65];
    int tile = blockIdx.x >> 3, kk = blockIdx.x & 7;
    int b = tile >> 6, t0 = (tile & 63) * 64;
    int tid = threadIdx.x;
#pragma unroll
    for (int i = 0; i < 16; i++) {
        int idx = i * 256 + tid;
        int k = idx >> 6, m = idx & 63;
        s[k * 65 + m] = x[((size_t)(b * DTOT + kk * 64 + k)) * TT + t0 + m];
    }
    __syncthreads();
    size_t base = (size_t)blockIdx.x * 8192;
    for (int q = tid; q < 512; q += 256) {
        int m = q >> 3, c = q & 7;
        uint32_t hp[4];
#pragma unroll
        for (int i = 0; i < 4; i++)
            hp[i] = pack_hi(s[(c * 8 + 2*i) * 65 + m], s[(c * 8 + 2*i + 1) * 65 + m]);
        uint32_t off = (uint32_t)m * 128 + ((uint32_t)(c ^ (m & 7)) << 4);
        *(uint4*)(g_A + base + off) = make_uint4(hp[0], hp[1], hp[2], hp[3]);
    }
}

// ---------------------------------------------------------------------------
// coarse: R12 config + DEDICATED PRODUCER WARP (warp 8 of 9)
// warps 0-7: warp tile 32x32 (2M x 4N) consume loop (no refill duty)
// ---------------------------------------------------------------------------
__global__ __launch_bounds__(288, 2)
void coarse_kernel() {
    extern __shared__ unsigned char dynraw[];
    __shared__ __align__(8) unsigned long long bars[2 * NSLOT];

    uint32_t raw = smem_u32(dynraw);
    uint32_t abase = (raw + 1023u) & ~1023u;
    float* esq_s = (float*)(dynraw + (abase - raw) + ESQ_OFF);
    uint32_t barF[NSLOT], barE[NSLOT];
#pragma unroll
    for (int i = 0; i < NSLOT; i++) {
        barF[i] = smem_u32(&bars[i]);
        barE[i] = smem_u32(&bars[NSLOT + i]);
    }

    int tid = threadIdx.x;
    int lane = tid & 31;
    int wid = tid >> 5;
    int tile = blockIdx.x;

    if (tid == 0) {
#pragma unroll
        for (int i = 0; i < NSLOT; i++) { mbar_init(barF[i], 1); mbar_init(barE[i], 8); }
    }
    for (int i = tid; i < SEM_SIZEV; i += 288) esq_s[i] = g_esq[i];
    __syncthreads();

    if (wid == 8) {
        // -------- producer warp: all 128 slot loads --------
        if (lane == 0) {
            const unsigned char* srcA = g_A + (size_t)tile * (8 * 8192);
            for (int s = 0; s < NC_COUNT * KK_COUNT; s++) {
                int slot = s & 3;                     // slot = kk&3 = s&3
                if (s >= NSLOT)
                    mbar_wait(barE[slot], (uint32_t)(((s >> 2) - 1) & 1));
                mbar_expect_tx(barF[slot], SLOT_BYTES);
                int kk = s & 7;
                int nc = s >> 3;
                bulk_g2s(abase + slot * SLOT_BYTES, srcA + (size_t)kk * 8192,
                         8192, barF[slot]);
                bulk_g2s(abase + slot * SLOT_BYTES + 8192,
                         g_B + (size_t)(nc * 8 + kk) * 16384, 16384, barF[slot]);
            }
        }
        return;
    }

    // -------- consumer warps 0-7 --------
    int warpM = wid >> 2, warpN = wid & 3;     // 2(M) x 4(N), warp 32x32

    uint32_t sw = lane & 7;
    uint32_t aRowOff = (uint32_t)(warpM * 32 + (lane & 15)) * 128;
    uint32_t aAdd = lane >> 4;
    uint32_t bRowOff = (uint32_t)(warpN * 32 + (lane & 7) + ((lane & 16) >> 1)) * 128;
    uint32_t bAdd = (lane >> 3) & 1;
    uint32_t caOff[4], cbOff[4];
#pragma unroll
    for (int j = 0; j < 4; j++) {
        caOff[j] = aRowOff + (uint32_t)(((2 * j + aAdd) ^ sw) << 4);
        cbOff[j] = 8192u + bRowOff + (uint32_t)(((2 * j + bAdd) ^ sw) << 4);
    }

    float tV[2][2][2];
    int   tI[2][2][2];
#pragma unroll
    for (int mi = 0; mi < 2; mi++)
#pragma unroll
        for (int h = 0; h < 2; h++) {
            tV[mi][h][0] = tV[mi][h][1] = 3.4e38f;
            tI[mi][h][0] = tI[mi][h][1] = 0;
        }

    for (int nc = 0; nc < NC_COUNT; nc++) {
        float acc[2][4][4];
#pragma unroll
        for (int mi = 0; mi < 2; mi++)
#pragma unroll
            for (int nf = 0; nf < 4; nf++)
#pragma unroll
                for (int e = 0; e < 4; e++) acc[mi][nf][e] = 0.0f;

#pragma unroll
        for (int kk = 0; kk < KK_COUNT; kk++) {
            int slot = kk & 3;
            uint32_t p = (uint32_t)(((nc << 1) + (kk >> 2)) & 1);
            mbar_wait(barF[slot], p);
            uint32_t sb = abase + slot * SLOT_BYTES;

#pragma unroll
            for (int j = 0; j < 4; j++) {
                uint32_t ar[2][4], br[2][4];
#pragma unroll
                for (int mi = 0; mi < 2; mi++)
                    LDSM4(ar[mi][0], ar[mi][1], ar[mi][2], ar[mi][3],
                          sb + caOff[j] + mi * 2048);
#pragma unroll
                for (int nf2 = 0; nf2 < 2; nf2++)
                    LDSM4(br[nf2][0], br[nf2][1], br[nf2][2], br[nf2][3],
                          sb + cbOff[j] + nf2 * 2048);
#pragma unroll
                for (int mi = 0; mi < 2; mi++)
#pragma unroll
                    for (int nf2 = 0; nf2 < 2; nf2++) {
                        MMA16816(acc[mi][2 * nf2],     ar[mi][0], ar[mi][1], ar[mi][2], ar[mi][3],
                                 br[nf2][0], br[nf2][1]);
                        MMA16816(acc[mi][2 * nf2 + 1], ar[mi][0], ar[mi][1], ar[mi][2], ar[mi][3],
                                 br[nf2][2], br[nf2][3]);
                    }
            }
            if (lane == 0) mbar_arrive(barE[slot]);
        }

        int cbase = nc * 128 + warpN * 32 + (lane & 3) * 2;
#pragma unroll
        for (int nf = 0; nf < 4; nf++) {
            float eq0 = esq_s[cbase + nf * 8 + 0];
            float eq1 = esq_s[cbase + nf * 8 + 1];
            int c0 = cbase + nf * 8, c1 = c0 + 1;
#pragma unroll
            for (int mi = 0; mi < 2; mi++) {
                top2_ins(eq0 - 2.0f * acc[mi][nf][0], c0, tV[mi][0], tI[mi][0]);
                top2_ins(eq1 - 2.0f * acc[mi][nf][1], c1, tV[mi][0], tI[mi][0]);
                top2_ins(eq0 - 2.0f * acc[mi][nf][2], c0, tV[mi][1], tI[mi][1]);
                top2_ins(eq1 - 2.0f * acc[mi][nf][3], c1, tV[mi][1], tI[mi][1]);
            }
        }
    }

    int slotIdx = (warpN * 4 + (lane & 3)) * 2;
#pragma unroll
    for (int mi = 0; mi < 2; mi++)
#pragma unroll
        for (int h = 0; h < 2; h++) {
            int r = tile * 64 + warpM * 32 + mi * 16 + h * 8 + (lane >> 2);
            size_t base = (size_t)r * 32 + slotIdx;
            g_candV[base]     = tV[mi][h][0];
            g_candV[base + 1] = tV[mi][h][1];
            g_candI[base]     = tI[mi][h][0];
            g_candI[base + 1] = tI[mi][h][1];
        }
}

// ---------------------------------------------------------------------------
// rescore: unchanged from R12 (single-survivor fast path + 2-way unroll)
// ---------------------------------------------------------------------------
#define XS_PITCH 513
#define DYN_RESCORE (32 * XS_PITCH * 4)

__global__ __launch_bounds__(1024)
void rescore_kernel(const float* __restrict__ x,
                    const float* __restrict__ probs_sem,
                    float* __restrict__ outq,
                    float* __restrict__ outc) {
    extern __shared__ float xs[];
    __shared__ int codes_s[32];

    int tid = threadIdx.x;
    int lane = tid & 31;
    int w = tid >> 5;
    int b = blockIdx.x >> 7;
    int t0 = (blockIdx.x & 127) * 32;

    const float* xb = x + (size_t)b * DTOT * TT + t0;

#pragma unroll
    for (int it = 0; it < 16; it++) {
        int idx = it * 1024 + tid;
        int d = idx >> 5, t = idx & 31;
        xs[t * XS_PITCH + d] = xb[(size_t)d * TT + t];
    }
    __syncthreads();

    int r = blockIdx.x * 32 + w;
    float candV = g_candV[(size_t)r * 32 + lane];
    int   candI = g_candI[(size_t)r * 32 + lane];
    float candE = g_esq[candI];

    float xsq = 0.0f;
#pragma unroll
    for (int i = 0; i < 16; i++) {
        float v = xs[w * XS_PITCH + i * 32 + lane];
        xsq += v * v;
    }
#pragma unroll
    for (int o = 16; o > 0; o >>= 1) xsq += __shfl_xor_sync(0xffffffffu, xsq, o);

    float delta = DELTA_C * sqrtf(xsq * candE);
    float ub = candV + delta;
#pragma unroll
    for (int o = 16; o > 0; o >>= 1) ub = fminf(ub, __shfl_xor_sync(0xffffffffu, ub, o));
    unsigned pm = __ballot_sync(0xffffffffu, candV - delta <= ub);

    int bestc;
    if (__popc(pm) == 1) {
        bestc = __shfl_sync(0xffffffffu, candI, __ffs(pm) - 1);
    } else {
        float bestd = 3.4e38f;
        bestc = SEM_SIZEV;
        while (pm) {
            int p0 = __ffs(pm) - 1;
            pm &= pm - 1;
            int has2 = (pm != 0u);
            int p1 = has2 ? (__ffs(pm) - 1) : p0;
            if (has2) pm &= pm - 1;

            int   c0 = __shfl_sync(0xffffffffu, candI, p0);
            float e0 = __shfl_sync(0xffffffffu, candE, p0);
            int   c1 = __shfl_sync(0xffffffffu, candI, p1);
            float e1 = __shfl_sync(0xffffffffu, candE, p1);
            const float* er0 = g_emb + (size_t)c0 * SEM_DIMV;
            const float* er1 = g_emb + (size_t)c1 * SEM_DIMV;
            float dot0 = 0.0f, dot1 = 0.0f;
#pragma unroll
            for (int i = 0; i < 16; i++) {
                float xv = xs[w * XS_PITCH + i * 32 + lane];
                dot0 += xv * er0[i * 32 + lane];
                dot1 += xv * er1[i * 32 + lane];
            }
#pragma unroll
            for (int o = 16; o > 0; o >>= 1) {
                dot0 += __shfl_xor_sync(0xffffffffu, dot0, o);
                dot1 += __shfl_xor_sync(0xffffffffu, dot1, o);
            }
            float d0 = e0 - 2.0f * dot0;
            if (d0 < bestd || (d0 == bestd && c0 < bestc)) { bestd = d0; bestc = c0; }
            if (has2) {
                float d1 = e1 - 2.0f * dot1;
                if (d1 < bestd || (d1 == bestd && c1 < bestc)) { bestd = d1; bestc = c1; }
            }
        }
    }
    if (lane == 0) {
        codes_s[w] = bestc;
        outc[(size_t)b * 33 * TT + t0 + w] = (float)bestc;
    }
    __syncthreads();

    float psem = probs_sem[b];
    float* outqb = outq + (size_t)b * DTOT * TT + t0;
    if (psem < 0.5f) {
        int c = codes_s[w];
        const float* er = g_emb + (size_t)c * SEM_DIMV;
        __syncthreads();
#pragma unroll
        for (int i = 0; i < 16; i++)
            xs[w * XS_PITCH + i * 32 + lane] = er[i * 32 + lane];
        __syncthreads();
    }
#pragma unroll
    for (int it = 0; it < 16; it++) {
        int idx = it * 1024 + tid;
        int d = idx >> 5, t = idx & 31;
        outqb[(size_t)d * TT + t] = xs[t * XS_PITCH + d];
    }
}

// ---------------------------------------------------------------------------
__global__ void aco_kernel(const float* __restrict__ x,
                           const float* __restrict__ noise,
                           const float* __restrict__ probs_aco,
                           float* __restrict__ outq,
                           float* __restrict__ outc) {
    int idx = blockIdx.x * blockDim.x + threadIdx.x;
    int t = idx & 4095;
    int rj = idx >> 12;
    int b = rj >> 5, j = rj & 31;

    float a = x[((size_t)b * DTOT + SEM_DIMV + j) * TT + t];
    float zb = tanhf(a) * HALFV;
    float pa = probs_aco[b];
    float zout;
    if (pa < 0.5f) {
        zout = rintf(zb);
    } else if (pa < 0.75f) {
        float ns = (noise[(size_t)rj * TT + t] * 2.0f - 1.0f) * (HALFV / 9.0f);
        zout = fminf(fmaxf(zb + ns, -HALFV), HALFV);
    } else {
        zout = zb;
    }
    float code = fminf(fmaxf(rintf(zout + HALFV), 0.0f), 8.0f);
    outq[((size_t)b * DTOT + SEM_DIMV + j) * TT + t] = zout * 0.25f;
    outc[((size_t)b * 33 + 1 + j) * TT + t] = code;
}

// ---------------------------------------------------------------------------
extern "C" void kernel_launch(void* const* d_in, const int* in_sizes, int n_in,
                              void* d_out, int out_size) {
    const float* x     = (const float*)d_in[0];
    const float* esum  = (const float*)d_in[1];
    const float* usage = (const float*)d_in[2];
    const float* noise = (const float*)d_in[3];
    const float* psem  = (const float*)d_in[4];
    const float* paco  = (const float*)d_in[5];

    float* outq = (float*)d_out;
    float* outc = outq + (size_t)BB * DTOT * TT;

    cudaFuncSetAttribute(coarse_kernel,
                         cudaFuncAttributeMaxDynamicSharedMemorySize, DYN_BYTES);
    cudaFuncSetAttribute(rescore_kernel,
                         cudaFuncAttributeMaxDynamicSharedMemorySize, DYN_RESCORE);

    prep_embB_kernel<<<SEM_SIZEV, 128>>>(esum, usage);
    prep_A_kernel<<<N_TILES * 8, 256>>>(x);
    coarse_kernel<<<N_TILES, 288, DYN_BYTES>>>();
    rescore_kernel<<<NROWS / 32, 1024, DYN_RESCORE>>>(x, psem, outq, outc);
    aco_kernel<<<(BB * ACO_DIMV * TT) / 256, 256>>>(x, noise, paco, outq, outc);
}